// round 14
// baseline (speedup 1.0000x reference)
#include <cuda_runtime.h>
#include <cuda_bf16.h>
#include <cstdint>

#define B_DIM 32
#define S_DIM 1024
#define H_DIM 1024
#define I_DIM 1024
#define KW    2048

// ---------------- scratch ----------------
__device__ float g_G[(size_t)3 * S_DIM * B_DIM * H_DIM];   // [g][t][b][h]
__device__ __nv_bfloat16 g_hbhi[2][B_DIM * H_DIM];         // h bf16 hi, [b][h]
__device__ __nv_bfloat16 g_hblo[2][B_DIM * H_DIM];         // h bf16 lo, [b][h]
__device__ unsigned g_cnt1[8 * 32];                        // group counters, 128B apart
__device__ unsigned g_cnt0 = 0;                            // root counter
__device__ unsigned g_barGen = 0;                          // published epoch
__device__ __nv_bfloat16 g_xhi[(size_t)B_DIM * S_DIM * I_DIM];
__device__ __nv_bfloat16 g_xlo[(size_t)B_DIM * S_DIM * I_DIM];
__device__ __nv_bfloat16 g_whi[(size_t)3 * H_DIM * I_DIM]; // rows g*1024+h, k<1024
__device__ __nv_bfloat16 g_wlo[(size_t)3 * H_DIM * I_DIM];

// ---------------- helpers ----------------
__device__ __forceinline__ uint32_t smem_u32(const void* p) {
    uint32_t a;
    asm("{ .reg .u64 t; cvta.to.shared.u64 t, %1; cvt.u32.u64 %0, t; }"
        : "=r"(a) : "l"(p));
    return a;
}
__device__ __forceinline__ void cpasync16(uint32_t s, const void* g) {
    asm volatile("cp.async.cg.shared.global [%0], [%1], 16;" :: "r"(s), "l"(g));
}
#define CP_COMMIT() asm volatile("cp.async.commit_group;" ::: "memory")
#define CP_WAIT1()  asm volatile("cp.async.wait_group 1;" ::: "memory")
#define CP_WAIT0()  asm volatile("cp.async.wait_group 0;" ::: "memory")

__device__ __forceinline__ void ldsm_x4(uint32_t& r0, uint32_t& r1,
                                        uint32_t& r2, uint32_t& r3,
                                        uint32_t addr) {
    asm volatile("ldmatrix.sync.aligned.m8n8.x4.shared.b16 {%0,%1,%2,%3}, [%4];"
                 : "=r"(r0), "=r"(r1), "=r"(r2), "=r"(r3) : "r"(addr));
}
__device__ __forceinline__ void mma16816(float* d, const uint32_t* a,
                                         uint32_t b0, uint32_t b1) {
    asm volatile("mma.sync.aligned.m16n8k16.row.col.f32.bf16.bf16.f32 "
                 "{%0,%1,%2,%3}, {%4,%5,%6,%7}, {%8,%9}, {%0,%1,%2,%3};"
                 : "+f"(d[0]), "+f"(d[1]), "+f"(d[2]), "+f"(d[3])
                 : "r"(a[0]), "r"(a[1]), "r"(a[2]), "r"(a[3]),
                   "r"(b0), "r"(b1));
}

// ---------------- conversion kernels ----------------
__global__ void cvt_x(const float* __restrict__ x) {
    size_t i = (size_t)blockIdx.x * blockDim.x + threadIdx.x;
    if (i < (size_t)B_DIM * S_DIM * I_DIM) {
        float v = x[i];
        __nv_bfloat16 h = __float2bfloat16(v);
        g_xhi[i] = h;
        g_xlo[i] = __float2bfloat16(v - __bfloat162float(h));
    }
}
__global__ void cvt_w(const float* __restrict__ Wf, const float* __restrict__ Wo,
                      const float* __restrict__ Wc) {
    size_t i = (size_t)blockIdx.x * blockDim.x + threadIdx.x;
    if (i < (size_t)3 * H_DIM * I_DIM) {
        int g = (int)(i / (H_DIM * I_DIM));
        size_t rem = i - (size_t)g * H_DIM * I_DIM;
        int h = (int)(rem >> 10), k = (int)(rem & 1023);
        const float* W = (g == 0) ? Wf : (g == 1 ? Wo : Wc);
        float v = W[(size_t)h * KW + k];
        __nv_bfloat16 hh = __float2bfloat16(v);
        g_whi[i] = hh;
        g_wlo[i] = __float2bfloat16(v - __bfloat162float(hh));
    }
}

// ---------------- Phase 1: mma.sync bf16 GEMM (3-term hi/lo), proven ----------------
#define APAD 40
#define ALO_OFF 5120
#define BHI_OFF 10240
#define BLO_OFF 15360
#define STG_ELEMS 20480
#define GSMEM_BYTES (2 * STG_ELEMS * 2)

extern __shared__ __nv_bfloat16 g_sm[];

__global__ __launch_bounds__(256, 1)
void mma_gemm(const float* __restrict__ bf, const float* __restrict__ bo,
              const float* __restrict__ bc) {
    uint32_t sbase = smem_u32(g_sm);
    const int tid = threadIdx.x, lane = tid & 31, warp = tid >> 5;
    const int wm = warp & 1, wn = warp >> 1;
    const int g  = blockIdx.x >> 3;
    const int h0 = (blockIdx.x & 7) * 128;
    const int rowBase = blockIdx.y * 128;
    const size_t aG = (size_t)rowBase * 1024;
    const size_t bG = ((size_t)g * 1024 + h0) * 1024;

    auto loadStage = [&](int st, int kt) {
        uint32_t sb = sbase + st * (STG_ELEMS * 2);
        for (int i = tid; i < 512; i += 256) {
            int r = i >> 2, c = i & 3;
            uint32_t off = (uint32_t)(r * APAD + c * 8) * 2;
            size_t src = (size_t)r * 1024 + kt + c * 8;
            cpasync16(sb + off,               g_xhi + aG + src);
            cpasync16(sb + ALO_OFF * 2 + off, g_xlo + aG + src);
            cpasync16(sb + BHI_OFF * 2 + off, g_whi + bG + src);
            cpasync16(sb + BLO_OFF * 2 + off, g_wlo + bG + src);
        }
    };

    float acc[4][4][4];
#pragma unroll
    for (int mi = 0; mi < 4; mi++)
#pragma unroll
        for (int ni = 0; ni < 4; ni++)
#pragma unroll
            for (int u = 0; u < 4; u++) acc[mi][ni][u] = 0.f;

    loadStage(0, 0);  CP_COMMIT();
    loadStage(1, 32); CP_COMMIT();

    const int aRow = wm * 64 + (lane & 15);
    const int aColB = (lane >> 4) * 16;
    const int bRow = wn * 32 + (lane & 7) + ((lane >> 4) << 3);
    const int bColB = ((lane >> 3) & 1) * 16;

    for (int kt = 0; kt < 32; kt++) {
        CP_WAIT1();
        __syncthreads();
        uint32_t sb = sbase + (kt & 1) * (STG_ELEMS * 2);
#pragma unroll
        for (int kk = 0; kk < 2; kk++) {
            uint32_t ahi[4][4], alo[4][4];
#pragma unroll
            for (int mi = 0; mi < 4; mi++) {
                uint32_t ad = sb + (uint32_t)((aRow + mi * 16) * APAD) * 2
                            + kk * 32 + aColB;
                ldsm_x4(ahi[mi][0], ahi[mi][1], ahi[mi][2], ahi[mi][3], ad);
                ldsm_x4(alo[mi][0], alo[mi][1], alo[mi][2], alo[mi][3],
                        ad + ALO_OFF * 2);
            }
            uint32_t bhi[4][2], blo[4][2];
#pragma unroll
            for (int nh = 0; nh < 2; nh++) {
                uint32_t bd = sb + BHI_OFF * 2
                            + (uint32_t)((bRow + nh * 16) * APAD) * 2
                            + kk * 32 + bColB;
                uint32_t r0, r1, r2, r3;
                ldsm_x4(r0, r1, r2, r3, bd);
                bhi[nh * 2][0] = r0; bhi[nh * 2][1] = r1;
                bhi[nh * 2 + 1][0] = r2; bhi[nh * 2 + 1][1] = r3;
                ldsm_x4(r0, r1, r2, r3, bd + (BLO_OFF - BHI_OFF) * 2);
                blo[nh * 2][0] = r0; blo[nh * 2][1] = r1;
                blo[nh * 2 + 1][0] = r2; blo[nh * 2 + 1][1] = r3;
            }
#pragma unroll
            for (int mi = 0; mi < 4; mi++)
#pragma unroll
                for (int ni = 0; ni < 4; ni++) {
                    mma16816(acc[mi][ni], ahi[mi], bhi[ni][0], bhi[ni][1]);
                    mma16816(acc[mi][ni], ahi[mi], blo[ni][0], blo[ni][1]);
                    mma16816(acc[mi][ni], alo[mi], bhi[ni][0], bhi[ni][1]);
                }
        }
        __syncthreads();
        if (kt + 2 < 32) loadStage(kt & 1, (kt + 2) * 32);
        CP_COMMIT();
    }

    const float* bias = (g == 0) ? bf : (g == 1 ? bo : bc);
    const int b    = rowBase >> 10;
    const int tLoc = rowBase & 1023;
#pragma unroll
    for (int ni = 0; ni < 4; ni++) {
        int h = h0 + wn * 32 + ni * 8 + (lane & 3) * 2;
        float bx = __ldg(&bias[h]), by = __ldg(&bias[h + 1]);
#pragma unroll
        for (int mi = 0; mi < 4; mi++) {
            int t0 = tLoc + wm * 64 + mi * 16 + (lane >> 2);
            float2 v0 = make_float2(acc[mi][ni][0] + bx, acc[mi][ni][1] + by);
            float2 v1 = make_float2(acc[mi][ni][2] + bx, acc[mi][ni][3] + by);
            *(float2*)&g_G[(((size_t)g * S_DIM + t0) * B_DIM + b) * H_DIM + h] = v0;
            *(float2*)&g_G[(((size_t)g * S_DIM + t0 + 8) * B_DIM + b) * H_DIM + h] = v1;
        }
    }
}

// ---------------- init h0 -> bf16 hi/lo [b][h] ----------------
__global__ void init_hb(const float* __restrict__ h0) {
    int i = blockIdx.x * blockDim.x + threadIdx.x;
    if (i < B_DIM * H_DIM) {
        float v = h0[i];
        __nv_bfloat16 hh = __float2bfloat16(v);
        g_hbhi[0][i] = hh;
        g_hblo[0][i] = __float2bfloat16(v - __bfloat162float(hh));
    }
}

// ---------------- Phase 2: persistent recurrence (tensor dot, pipelined) ----------------
#define NB_CTA 128
#define CPB    8
#define NTH    256
// smem byte offsets
#define SW_HI   0u
#define SW_LO   66048u          // 32 rows * 2064 B
#define SH_BASE 132096u         // 2 buffers x (hi 16896 + lo 16896)
#define HBUFSZ  33792u
#define HLO_OFF 16896u
#define PBUF_B  132096u         // alias over h buffers (dead at partials time)
#define CSM_B   199680u
#define TBUF_B  200704u
#define RSMEM_BYTES 201856u
#define WSTRB   2064            // sW row stride bytes (1032 bf16)
#define HSTRB   528             // sH quarter row stride bytes (264 bf16)
#define PSTR    34              // pbuf row stride floats

__device__ __forceinline__ float sigm_f(float x) {
    return __fdividef(1.f, 1.f + __expf(-x));
}
__device__ __forceinline__ float tanh_f(float x) {
    return 1.f - __fdividef(2.f, 1.f + __expf(2.f * x));
}

extern __shared__ char r_sm[];

__global__ __launch_bounds__(NTH, 1)
void lstm_recurrent(const float* __restrict__ Wf, const float* __restrict__ Wo,
                    const float* __restrict__ Wc, const float* __restrict__ c0,
                    float* __restrict__ out, int out_size) {
    __shared__ unsigned s_base;
    const uint32_t sA = smem_u32(r_sm);
    float* csm  = (float*)(r_sm + CSM_B);     // [cc*32 + bb]
    float* tbuf = (float*)(r_sm + TBUF_B);    // [bb*9 + cc]
    float* pbuf = (float*)(r_sm + PBUF_B);    // [w][row(34)][batch]

    const int tid  = threadIdx.x;
    const int bid  = blockIdx.x;
    const int c0col = bid * CPB;
    const int lane = tid & 31;
    const int w    = tid >> 5;                // 8 warps
    const int grp  = bid >> 4;                // 8 barrier groups of 16 CTAs

    if (tid == 0) s_base = *(volatile unsigned*)&g_barGen;  // epoch base

    // ---- one-time: recurrent weights fp32 -> bf16 hi/lo into smem ----
    for (int i = tid; i < 24 * 1024; i += NTH) {
        int row = i >> 10, k = i & 1023;
        int gg = row >> 3, cc = row & 7;
        const float* Wsel = (gg == 0) ? Wf : (gg == 1 ? Wo : Wc);
        float v = Wsel[(size_t)(c0col + cc) * KW + I_DIM + k];
        __nv_bfloat16 hh = __float2bfloat16(v);
        __nv_bfloat16 hl = __float2bfloat16(v - __bfloat162float(hh));
        *(__nv_bfloat16*)(r_sm + SW_HI + row * WSTRB + k * 2) = hh;
        *(__nv_bfloat16*)(r_sm + SW_LO + row * WSTRB + k * 2) = hl;
    }
    for (int i = tid; i < 8 * (WSTRB / 4); i += NTH) {
        int row = 24 + i / (WSTRB / 4), wd = i % (WSTRB / 4);
        *(uint32_t*)(r_sm + SW_HI + row * WSTRB + wd * 4) = 0u;
        *(uint32_t*)(r_sm + SW_LO + row * WSTRB + wd * 4) = 0u;
    }
    for (int i = tid; i < B_DIM * CPB; i += NTH) {
        int cc = i >> 5, bb = i & 31;
        csm[cc * 32 + bb] = c0[bb * H_DIM + c0col + cc];
    }
    __syncthreads();
    const unsigned base = s_base;

    const bool wantTail = (out_size >= (B_DIM * S_DIM * H_DIM + 2 * B_DIM * H_DIM));

    // ldmatrix lane addressing (form copied from passing R13)
    const int aRB = (lane & 15) * WSTRB + ((lane >> 4) << 4);
    const int bRB = ((lane & 7) + ((lane >> 4) << 3)) * HSTRB
                  + (((lane >> 3) & 1) << 4);

    for (int t = 0; t < S_DIM; t++) {
        const int ep = t & 1, epn = ep ^ 1;
        const __nv_bfloat16* hhiG = g_hbhi[ep];
        const __nv_bfloat16* hloG = g_hblo[ep];

        // stage one K-quarter (256 k) of h hi/lo into buffer `buf`
        auto stageQ = [&](int q, int buf) {
            const uint32_t dst = sA + SH_BASE + (uint32_t)buf * HBUFSZ;
            for (int i = tid; i < 1024; i += NTH) {
                int row = i >> 5, c = i & 31;
                size_t gsrc = (size_t)row * 1024 + q * 256 + c * 8;
                uint32_t o = (uint32_t)(row * HSTRB + c * 16);
                cpasync16(dst + o,           hhiG + gsrc);
                cpasync16(dst + HLO_OFF + o, hloG + gsrc);
            }
        };

        // prefetch x-part pre-activations (warp -> cc, lane -> bb)
        float gxr0, gxr1, gxr2;
        {
            size_t ofs = ((size_t)t * B_DIM + lane) * H_DIM + c0col + w;
            const size_t GSTR = (size_t)S_DIM * B_DIM * H_DIM;
            gxr0 = __ldg(&g_G[ofs]);
            gxr1 = __ldg(&g_G[GSTR + ofs]);
            gxr2 = __ldg(&g_G[2 * GSTR + ofs]);
        }

        float acc[2][4][4];
#pragma unroll
        for (int mi = 0; mi < 2; mi++)
#pragma unroll
            for (int ni = 0; ni < 4; ni++)
#pragma unroll
                for (int u = 0; u < 4; u++) acc[mi][ni][u] = 0.f;

        stageQ(0, 0); CP_COMMIT();

#pragma unroll
        for (int q = 0; q < 4; q++) {
            if (q < 3) { stageQ(q + 1, (q + 1) & 1); CP_COMMIT(); CP_WAIT1(); }
            else       { CP_WAIT0(); }
            __syncthreads();

            const uint32_t hb = sA + SH_BASE + (uint32_t)(q & 1) * HBUFSZ;
#pragma unroll
            for (int kk = 0; kk < 2; kk++) {
                const uint32_t colWb = (uint32_t)(q * 16 + w * 2 + kk) * 32;
                const uint32_t colHb = (uint32_t)(w * 2 + kk) * 32;
                uint32_t whi[2][4], wlo[2][4];
#pragma unroll
                for (int mi = 0; mi < 2; mi++) {
                    uint32_t ad = sA + SW_HI + (uint32_t)(mi * 16 * WSTRB)
                                + aRB + colWb;
                    ldsm_x4(whi[mi][0], whi[mi][1], whi[mi][2], whi[mi][3], ad);
                    ldsm_x4(wlo[mi][0], wlo[mi][1], wlo[mi][2], wlo[mi][3],
                            ad + (SW_LO - SW_HI));
                }
                uint32_t hhi[4][2], hlo[4][2];
#pragma unroll
                for (int nbk = 0; nbk < 2; nbk++) {
                    uint32_t bd = hb + (uint32_t)(nbk * 16 * HSTRB) + bRB + colHb;
                    uint32_t r0, r1, r2, r3;
                    ldsm_x4(r0, r1, r2, r3, bd);
                    hhi[nbk * 2][0] = r0; hhi[nbk * 2][1] = r1;
                    hhi[nbk * 2 + 1][0] = r2; hhi[nbk * 2 + 1][1] = r3;
                    ldsm_x4(r0, r1, r2, r3, bd + HLO_OFF);
                    hlo[nbk * 2][0] = r0; hlo[nbk * 2][1] = r1;
                    hlo[nbk * 2 + 1][0] = r2; hlo[nbk * 2 + 1][1] = r3;
                }
#pragma unroll
                for (int mi = 0; mi < 2; mi++)
#pragma unroll
                    for (int ni = 0; ni < 4; ni++)
                        mma16816(acc[mi][ni], whi[mi], hhi[ni][0], hhi[ni][1]);
#pragma unroll
                for (int mi = 0; mi < 2; mi++)
#pragma unroll
                    for (int ni = 0; ni < 4; ni++)
                        mma16816(acc[mi][ni], whi[mi], hlo[ni][0], hlo[ni][1]);
#pragma unroll
                for (int mi = 0; mi < 2; mi++)
#pragma unroll
                    for (int ni = 0; ni < 4; ni++)
                        mma16816(acc[mi][ni], wlo[mi], hhi[ni][0], hhi[ni][1]);
            }
            __syncthreads();   // buffer reads done before next overwrite
        }

        // ---- partials to smem: pbuf[w][gatecol][batch] ----
#pragma unroll
        for (int mi = 0; mi < 2; mi++) {
            int row0 = mi * 16 + (lane >> 2);
#pragma unroll
            for (int ni = 0; ni < 4; ni++) {
                int col0 = ni * 8 + (lane & 3) * 2;
                float* pb = pbuf + w * (32 * PSTR);
                *(float2*)&pb[row0 * PSTR + col0] =
                    make_float2(acc[mi][ni][0], acc[mi][ni][1]);
                *(float2*)&pb[(row0 + 8) * PSTR + col0] =
                    make_float2(acc[mi][ni][2], acc[mi][ni][3]);
            }
        }
        __syncthreads();

        // ---- reduce 8 partials + gate math (warp = cc, lane = bb) ----
        {
            const int cc = w, bb = lane;
            float pre0 = gxr0, pre1 = gxr1, pre2 = gxr2;
#pragma unroll
            for (int u = 0; u < 8; u++) {
                const float* pb = pbuf + u * (32 * PSTR) + bb;
                pre0 += pb[(cc)      * PSTR];
                pre1 += pb[(8 + cc)  * PSTR];
                pre2 += pb[(16 + cc) * PSTR];
            }
            float f  = sigm_f(pre0);
            float o  = sigm_f(pre1);
            float ch = tanh_f(pre2);
            float cold = csm[cc * 32 + bb];
            float cn = f * (cold - ch) + ch;
            float hn = o * tanh_f(cn);
            csm[cc * 32 + bb] = cn;
            tbuf[bb * 9 + cc] = hn;

            if (t == S_DIM - 1 && wantTail) {
                int colg = c0col + cc;
                size_t base2 = (size_t)B_DIM * S_DIM * H_DIM;
                out[base2 + (size_t)bb * H_DIM + colg] = hn;
                out[base2 + (size_t)B_DIM * H_DIM + (size_t)bb * H_DIM + colg] = cn;
            }
        }
        __syncthreads();

        // ---- coalesced out store: 32 threads x 2 STG.128 ----
        if (tid < 32) {
            const int bb = tid;
            float4 v0 = make_float4(tbuf[bb * 9 + 0], tbuf[bb * 9 + 1],
                                    tbuf[bb * 9 + 2], tbuf[bb * 9 + 3]);
            float4 v1 = make_float4(tbuf[bb * 9 + 4], tbuf[bb * 9 + 5],
                                    tbuf[bb * 9 + 6], tbuf[bb * 9 + 7]);
            float* op = &out[((size_t)bb * S_DIM + t) * H_DIM + c0col];
            *(float4*)op       = v0;
            *(float4*)(op + 4) = v1;
        }

        // ---- h -> bf16 hi/lo, coalesced store to next epoch ----
        {
            int bb = tid >> 3, cc = tid & 7;
            float v = tbuf[bb * 9 + cc];
            __nv_bfloat16 hh = __float2bfloat16(v);
            __nv_bfloat16 hl = __float2bfloat16(v - __bfloat162float(hh));
            unsigned short uh = *(unsigned short*)&hh;
            unsigned short ul = *(unsigned short*)&hl;
            size_t go = (size_t)bb * H_DIM + c0col + cc;
            asm volatile("st.global.cg.u16 [%0], %1;"
                         :: "l"(&g_hbhi[epn][go]), "h"(uh) : "memory");
            asm volatile("st.global.cg.u16 [%0], %1;"
                         :: "l"(&g_hblo[epn][go]), "h"(ul) : "memory");
        }

        // ---- two-level grid barrier (skip after final step) ----
        if (t < S_DIM - 1) {
            __syncthreads();
            const unsigned tgt = base + (unsigned)t + 1u;
            if (tid == 0) {
                __threadfence();
                unsigned old = atomicAdd(&g_cnt1[grp * 32], 1u);
                if (old == tgt * 16u - 1u) {            // last in group
                    unsigned old2 = atomicAdd(&g_cnt0, 1u);
                    if (old2 == tgt * 8u - 1u) {        // last group
                        __threadfence();
                        *(volatile unsigned*)&g_barGen = tgt;
                    }
                }
                while ((int)(*(volatile unsigned*)&g_barGen - tgt) < 0)
                    __nanosleep(20);
                __threadfence();
            }
            __syncthreads();
        }
    }
}

// ---------------- launch ----------------
extern "C" void kernel_launch(void* const* d_in, const int* in_sizes, int n_in,
                              void* d_out, int out_size) {
    const float* x  = (const float*)d_in[0];
    const float* h0 = (const float*)d_in[1];
    const float* c0 = (const float*)d_in[2];
    const float* Wf = (const float*)d_in[3];
    const float* bf = (const float*)d_in[4];
    const float* Wo = (const float*)d_in[5];
    const float* bo = (const float*)d_in[6];
    const float* Wc = (const float*)d_in[7];
    const float* bc = (const float*)d_in[8];
    float* out = (float*)d_out;

    cudaFuncSetAttribute(mma_gemm,
                         cudaFuncAttributeMaxDynamicSharedMemorySize, GSMEM_BYTES);
    cudaFuncSetAttribute(lstm_recurrent,
                         cudaFuncAttributeMaxDynamicSharedMemorySize, RSMEM_BYTES);

    cvt_x<<<(B_DIM * S_DIM * I_DIM + 255) / 256, 256>>>(x);
    cvt_w<<<(3 * H_DIM * I_DIM + 255) / 256, 256>>>(Wf, Wo, Wc);
    mma_gemm<<<dim3(24, 256), 256, GSMEM_BYTES>>>(bf, bo, bc);
    init_hb<<<(B_DIM * H_DIM + 255) / 256, 256>>>(h0);
    lstm_recurrent<<<NB_CTA, NTH, RSMEM_BYTES>>>(Wf, Wo, Wc, c0, out, out_size);
}

// round 15
// speedup vs baseline: 1.0339x; 1.0339x over previous
#include <cuda_runtime.h>
#include <cuda_bf16.h>
#include <cstdint>

#define B_DIM 32
#define S_DIM 1024
#define H_DIM 1024
#define I_DIM 1024
#define KW    2048

// ---------------- scratch ----------------
__device__ float g_G[(size_t)3 * S_DIM * B_DIM * H_DIM];   // [g][t][b][h]
__device__ __nv_bfloat16 g_hbhi[2][B_DIM * H_DIM];         // h bf16 hi, [b][h]
__device__ __nv_bfloat16 g_hblo[2][B_DIM * H_DIM];         // h bf16 lo, [b][h]
__device__ unsigned g_qcnt[4 * 64];                        // per-group counters, 256B apart
__device__ unsigned g_base = 0;                            // per-launch epoch base
__device__ __nv_bfloat16 g_xhi[(size_t)B_DIM * S_DIM * I_DIM];
__device__ __nv_bfloat16 g_xlo[(size_t)B_DIM * S_DIM * I_DIM];
__device__ __nv_bfloat16 g_whi[(size_t)3 * H_DIM * I_DIM]; // rows g*1024+h, k<1024
__device__ __nv_bfloat16 g_wlo[(size_t)3 * H_DIM * I_DIM];

// ---------------- helpers ----------------
__device__ __forceinline__ uint32_t smem_u32(const void* p) {
    uint32_t a;
    asm("{ .reg .u64 t; cvta.to.shared.u64 t, %1; cvt.u32.u64 %0, t; }"
        : "=r"(a) : "l"(p));
    return a;
}
__device__ __forceinline__ void cpasync16(uint32_t s, const void* g) {
    asm volatile("cp.async.cg.shared.global [%0], [%1], 16;" :: "r"(s), "l"(g));
}
#define CP_COMMIT() asm volatile("cp.async.commit_group;" ::: "memory")
#define CP_WAIT1()  asm volatile("cp.async.wait_group 1;" ::: "memory")
#define CP_WAIT0()  asm volatile("cp.async.wait_group 0;" ::: "memory")

__device__ __forceinline__ void ldsm_x4(uint32_t& r0, uint32_t& r1,
                                        uint32_t& r2, uint32_t& r3,
                                        uint32_t addr) {
    asm volatile("ldmatrix.sync.aligned.m8n8.x4.shared.b16 {%0,%1,%2,%3}, [%4];"
                 : "=r"(r0), "=r"(r1), "=r"(r2), "=r"(r3) : "r"(addr));
}
__device__ __forceinline__ void mma16816(float* d, const uint32_t* a,
                                         uint32_t b0, uint32_t b1) {
    asm volatile("mma.sync.aligned.m16n8k16.row.col.f32.bf16.bf16.f32 "
                 "{%0,%1,%2,%3}, {%4,%5,%6,%7}, {%8,%9}, {%0,%1,%2,%3};"
                 : "+f"(d[0]), "+f"(d[1]), "+f"(d[2]), "+f"(d[3])
                 : "r"(a[0]), "r"(a[1]), "r"(a[2]), "r"(a[3]),
                   "r"(b0), "r"(b1));
}

// ---------------- conversion kernels ----------------
__global__ void cvt_x(const float* __restrict__ x) {
    size_t i = (size_t)blockIdx.x * blockDim.x + threadIdx.x;
    if (i < (size_t)B_DIM * S_DIM * I_DIM) {
        float v = x[i];
        __nv_bfloat16 h = __float2bfloat16(v);
        g_xhi[i] = h;
        g_xlo[i] = __float2bfloat16(v - __bfloat162float(h));
    }
}
__global__ void cvt_w(const float* __restrict__ Wf, const float* __restrict__ Wo,
                      const float* __restrict__ Wc) {
    size_t i = (size_t)blockIdx.x * blockDim.x + threadIdx.x;
    if (i < (size_t)3 * H_DIM * I_DIM) {
        int g = (int)(i / (H_DIM * I_DIM));
        size_t rem = i - (size_t)g * H_DIM * I_DIM;
        int h = (int)(rem >> 10), k = (int)(rem & 1023);
        const float* W = (g == 0) ? Wf : (g == 1 ? Wo : Wc);
        float v = W[(size_t)h * KW + k];
        __nv_bfloat16 hh = __float2bfloat16(v);
        g_whi[i] = hh;
        g_wlo[i] = __float2bfloat16(v - __bfloat162float(hh));
    }
}

// ---------------- Phase 1: mma.sync bf16 GEMM (3-term hi/lo), proven ----------------
#define APAD 40
#define ALO_OFF 5120
#define BHI_OFF 10240
#define BLO_OFF 15360
#define STG_ELEMS 20480
#define GSMEM_BYTES (2 * STG_ELEMS * 2)

extern __shared__ __nv_bfloat16 g_sm[];

__global__ __launch_bounds__(256, 1)
void mma_gemm(const float* __restrict__ bf, const float* __restrict__ bo,
              const float* __restrict__ bc) {
    uint32_t sbase = smem_u32(g_sm);
    const int tid = threadIdx.x, lane = tid & 31, warp = tid >> 5;
    const int wm = warp & 1, wn = warp >> 1;
    const int g  = blockIdx.x >> 3;
    const int h0 = (blockIdx.x & 7) * 128;
    const int rowBase = blockIdx.y * 128;
    const size_t aG = (size_t)rowBase * 1024;
    const size_t bG = ((size_t)g * 1024 + h0) * 1024;

    auto loadStage = [&](int st, int kt) {
        uint32_t sb = sbase + st * (STG_ELEMS * 2);
        for (int i = tid; i < 512; i += 256) {
            int r = i >> 2, c = i & 3;
            uint32_t off = (uint32_t)(r * APAD + c * 8) * 2;
            size_t src = (size_t)r * 1024 + kt + c * 8;
            cpasync16(sb + off,               g_xhi + aG + src);
            cpasync16(sb + ALO_OFF * 2 + off, g_xlo + aG + src);
            cpasync16(sb + BHI_OFF * 2 + off, g_whi + bG + src);
            cpasync16(sb + BLO_OFF * 2 + off, g_wlo + bG + src);
        }
    };

    float acc[4][4][4];
#pragma unroll
    for (int mi = 0; mi < 4; mi++)
#pragma unroll
        for (int ni = 0; ni < 4; ni++)
#pragma unroll
            for (int u = 0; u < 4; u++) acc[mi][ni][u] = 0.f;

    loadStage(0, 0);  CP_COMMIT();
    loadStage(1, 32); CP_COMMIT();

    const int aRow = wm * 64 + (lane & 15);
    const int aColB = (lane >> 4) * 16;
    const int bRow = wn * 32 + (lane & 7) + ((lane >> 4) << 3);
    const int bColB = ((lane >> 3) & 1) * 16;

    for (int kt = 0; kt < 32; kt++) {
        CP_WAIT1();
        __syncthreads();
        uint32_t sb = sbase + (kt & 1) * (STG_ELEMS * 2);
#pragma unroll
        for (int kk = 0; kk < 2; kk++) {
            uint32_t ahi[4][4], alo[4][4];
#pragma unroll
            for (int mi = 0; mi < 4; mi++) {
                uint32_t ad = sb + (uint32_t)((aRow + mi * 16) * APAD) * 2
                            + kk * 32 + aColB;
                ldsm_x4(ahi[mi][0], ahi[mi][1], ahi[mi][2], ahi[mi][3], ad);
                ldsm_x4(alo[mi][0], alo[mi][1], alo[mi][2], alo[mi][3],
                        ad + ALO_OFF * 2);
            }
            uint32_t bhi[4][2], blo[4][2];
#pragma unroll
            for (int nh = 0; nh < 2; nh++) {
                uint32_t bd = sb + BHI_OFF * 2
                            + (uint32_t)((bRow + nh * 16) * APAD) * 2
                            + kk * 32 + bColB;
                uint32_t r0, r1, r2, r3;
                ldsm_x4(r0, r1, r2, r3, bd);
                bhi[nh * 2][0] = r0; bhi[nh * 2][1] = r1;
                bhi[nh * 2 + 1][0] = r2; bhi[nh * 2 + 1][1] = r3;
                ldsm_x4(r0, r1, r2, r3, bd + (BLO_OFF - BHI_OFF) * 2);
                blo[nh * 2][0] = r0; blo[nh * 2][1] = r1;
                blo[nh * 2 + 1][0] = r2; blo[nh * 2 + 1][1] = r3;
            }
#pragma unroll
            for (int mi = 0; mi < 4; mi++)
#pragma unroll
                for (int ni = 0; ni < 4; ni++) {
                    mma16816(acc[mi][ni], ahi[mi], bhi[ni][0], bhi[ni][1]);
                    mma16816(acc[mi][ni], ahi[mi], blo[ni][0], blo[ni][1]);
                    mma16816(acc[mi][ni], alo[mi], bhi[ni][0], bhi[ni][1]);
                }
        }
        __syncthreads();
        if (kt + 2 < 32) loadStage(kt & 1, (kt + 2) * 32);
        CP_COMMIT();
    }

    const float* bias = (g == 0) ? bf : (g == 1 ? bo : bc);
    const int b    = rowBase >> 10;
    const int tLoc = rowBase & 1023;
#pragma unroll
    for (int ni = 0; ni < 4; ni++) {
        int h = h0 + wn * 32 + ni * 8 + (lane & 3) * 2;
        float bx = __ldg(&bias[h]), by = __ldg(&bias[h + 1]);
#pragma unroll
        for (int mi = 0; mi < 4; mi++) {
            int t0 = tLoc + wm * 64 + mi * 16 + (lane >> 2);
            float2 v0 = make_float2(acc[mi][ni][0] + bx, acc[mi][ni][1] + by);
            float2 v1 = make_float2(acc[mi][ni][2] + bx, acc[mi][ni][3] + by);
            *(float2*)&g_G[(((size_t)g * S_DIM + t0) * B_DIM + b) * H_DIM + h] = v0;
            *(float2*)&g_G[(((size_t)g * S_DIM + t0 + 8) * B_DIM + b) * H_DIM + h] = v1;
        }
    }
}

// ---------------- init h0 -> bf16 hi/lo [b][h]; snapshot epoch base ----------------
__global__ void init_hb(const float* __restrict__ h0) {
    int i = blockIdx.x * blockDim.x + threadIdx.x;
    if (i < B_DIM * H_DIM) {
        float v = h0[i];
        __nv_bfloat16 hh = __float2bfloat16(v);
        g_hbhi[0][i] = hh;
        g_hblo[0][i] = __float2bfloat16(v - __bfloat162float(hh));
    }
    if (blockIdx.x == 0 && threadIdx.x == 0)
        g_base = *(volatile unsigned*)&g_qcnt[0];
}

// ---------------- Phase 2: persistent recurrence (tensor dot, gated pipeline) ----------------
#define NB_CTA 128
#define CPB    8
#define NTH    256
// smem byte offsets
#define SW_HI   0u
#define SW_LO   66048u          // 32 rows * 2064 B
#define SH_BASE 132096u         // 2 buffers x (hi 16896 + lo 16896)
#define HBUFSZ  33792u
#define HLO_OFF 16896u
#define PBUF_B  132096u         // alias over h buffers (dead at partials time)
#define CSM_B   199680u
#define TBUF_B  200704u
#define RSMEM_BYTES 201856u
#define WSTRB   2064            // sW row stride bytes (1032 bf16)
#define HSTRB   528             // sH quarter row stride bytes (264 bf16)
#define PSTR    34              // pbuf row stride floats

__device__ __forceinline__ float sigm_f(float x) {
    return __fdividef(1.f, 1.f + __expf(-x));
}
__device__ __forceinline__ float tanh_f(float x) {
    return 1.f - __fdividef(2.f, 1.f + __expf(2.f * x));
}

extern __shared__ char r_sm[];

__global__ __launch_bounds__(NTH, 1)
void lstm_recurrent(const float* __restrict__ Wf, const float* __restrict__ Wo,
                    const float* __restrict__ Wc, const float* __restrict__ c0,
                    float* __restrict__ out, int out_size) {
    __shared__ unsigned s_base;
    const uint32_t sA = smem_u32(r_sm);
    float* csm  = (float*)(r_sm + CSM_B);     // [cc*32 + bb]
    float* tbuf = (float*)(r_sm + TBUF_B);    // [bb*9 + cc]
    float* pbuf = (float*)(r_sm + PBUF_B);    // [w][row(34)][batch]

    const int tid  = threadIdx.x;
    const int bid  = blockIdx.x;
    const int c0col = bid * CPB;
    const int lane = tid & 31;
    const int w    = tid >> 5;                // 8 warps
    const int grp  = bid >> 5;                // 4 producer groups of 32 CTAs

    if (tid == 0) s_base = *(volatile unsigned*)&g_base;

    // ---- one-time: recurrent weights fp32 -> bf16 hi/lo into smem ----
    for (int i = tid; i < 24 * 1024; i += NTH) {
        int row = i >> 10, k = i & 1023;
        int gg = row >> 3, cc = row & 7;
        const float* Wsel = (gg == 0) ? Wf : (gg == 1 ? Wo : Wc);
        float v = Wsel[(size_t)(c0col + cc) * KW + I_DIM + k];
        __nv_bfloat16 hh = __float2bfloat16(v);
        __nv_bfloat16 hl = __float2bfloat16(v - __bfloat162float(hh));
        *(__nv_bfloat16*)(r_sm + SW_HI + row * WSTRB + k * 2) = hh;
        *(__nv_bfloat16*)(r_sm + SW_LO + row * WSTRB + k * 2) = hl;
    }
    for (int i = tid; i < 8 * (WSTRB / 4); i += NTH) {
        int row = 24 + i / (WSTRB / 4), wd = i % (WSTRB / 4);
        *(uint32_t*)(r_sm + SW_HI + row * WSTRB + wd * 4) = 0u;
        *(uint32_t*)(r_sm + SW_LO + row * WSTRB + wd * 4) = 0u;
    }
    for (int i = tid; i < B_DIM * CPB; i += NTH) {
        int cc = i >> 5, bb = i & 31;
        csm[cc * 32 + bb] = c0[bb * H_DIM + c0col + cc];
    }
    __syncthreads();
    const unsigned gbase = s_base;

    const bool wantTail = (out_size >= (B_DIM * S_DIM * H_DIM + 2 * B_DIM * H_DIM));

    // ldmatrix lane addressing (form copied from passing R13)
    const int aRB = (lane & 15) * WSTRB + ((lane >> 4) << 4);
    const int bRB = ((lane & 7) + ((lane >> 4) << 3)) * HSTRB
                  + (((lane >> 3) & 1) << 4);

    for (int t = 0; t < S_DIM; t++) {
        const int ep = t & 1, epn = ep ^ 1;
        const __nv_bfloat16* hhiG = g_hbhi[ep];
        const __nv_bfloat16* hloG = g_hblo[ep];

        // gate: producers of quarter q must have finished step t-1
        auto gateQ = [&](int q) {
            if (t > 0) {
                if (tid == 0) {
                    const unsigned tgt = gbase + 32u * (unsigned)t;
                    unsigned v;
                    while (true) {
                        asm volatile("ld.global.acquire.gpu.b32 %0, [%1];"
                                     : "=r"(v) : "l"(&g_qcnt[q * 64]));
                        if ((int)(v - tgt) >= 0) break;
                        __nanosleep(20);
                    }
                }
                __syncthreads();
            }
        };

        // stage one K-quarter (256 k) of h hi/lo into buffer `buf`
        auto stageQ = [&](int q, int buf) {
            const uint32_t dst = sA + SH_BASE + (uint32_t)buf * HBUFSZ;
            for (int i = tid; i < 1024; i += NTH) {
                int row = i >> 5, c = i & 31;
                size_t gsrc = (size_t)row * 1024 + q * 256 + c * 8;
                uint32_t o = (uint32_t)(row * HSTRB + c * 16);
                cpasync16(dst + o,           hhiG + gsrc);
                cpasync16(dst + HLO_OFF + o, hloG + gsrc);
            }
        };

        // prefetch x-part pre-activations (warp -> cc, lane -> bb)
        float gxr0, gxr1, gxr2;
        {
            size_t ofs = ((size_t)t * B_DIM + lane) * H_DIM + c0col + w;
            const size_t GSTR = (size_t)S_DIM * B_DIM * H_DIM;
            gxr0 = __ldg(&g_G[ofs]);
            gxr1 = __ldg(&g_G[GSTR + ofs]);
            gxr2 = __ldg(&g_G[2 * GSTR + ofs]);
        }

        float acc[2][4][4];
#pragma unroll
        for (int mi = 0; mi < 2; mi++)
#pragma unroll
            for (int ni = 0; ni < 4; ni++)
#pragma unroll
                for (int u = 0; u < 4; u++) acc[mi][ni][u] = 0.f;

        gateQ(0);
        stageQ(0, 0); CP_COMMIT();

#pragma unroll
        for (int q = 0; q < 4; q++) {
            if (q < 3) {
                gateQ(q + 1);
                stageQ(q + 1, (q + 1) & 1); CP_COMMIT(); CP_WAIT1();
            } else {
                CP_WAIT0();
            }
            __syncthreads();

            const uint32_t hb = sA + SH_BASE + (uint32_t)(q & 1) * HBUFSZ;
#pragma unroll
            for (int kk = 0; kk < 2; kk++) {
                const uint32_t colWb = (uint32_t)(q * 16 + w * 2 + kk) * 32;
                const uint32_t colHb = (uint32_t)(w * 2 + kk) * 32;
                uint32_t whi[2][4], wlo[2][4];
#pragma unroll
                for (int mi = 0; mi < 2; mi++) {
                    uint32_t ad = sA + SW_HI + (uint32_t)(mi * 16 * WSTRB)
                                + aRB + colWb;
                    ldsm_x4(whi[mi][0], whi[mi][1], whi[mi][2], whi[mi][3], ad);
                    ldsm_x4(wlo[mi][0], wlo[mi][1], wlo[mi][2], wlo[mi][3],
                            ad + (SW_LO - SW_HI));
                }
                uint32_t hhi[4][2], hlo[4][2];
#pragma unroll
                for (int nbk = 0; nbk < 2; nbk++) {
                    uint32_t bd = hb + (uint32_t)(nbk * 16 * HSTRB) + bRB + colHb;
                    uint32_t r0, r1, r2, r3;
                    ldsm_x4(r0, r1, r2, r3, bd);
                    hhi[nbk * 2][0] = r0; hhi[nbk * 2][1] = r1;
                    hhi[nbk * 2 + 1][0] = r2; hhi[nbk * 2 + 1][1] = r3;
                    ldsm_x4(r0, r1, r2, r3, bd + HLO_OFF);
                    hlo[nbk * 2][0] = r0; hlo[nbk * 2][1] = r1;
                    hlo[nbk * 2 + 1][0] = r2; hlo[nbk * 2 + 1][1] = r3;
                }
#pragma unroll
                for (int mi = 0; mi < 2; mi++)
#pragma unroll
                    for (int ni = 0; ni < 4; ni++)
                        mma16816(acc[mi][ni], whi[mi], hhi[ni][0], hhi[ni][1]);
#pragma unroll
                for (int mi = 0; mi < 2; mi++)
#pragma unroll
                    for (int ni = 0; ni < 4; ni++)
                        mma16816(acc[mi][ni], whi[mi], hlo[ni][0], hlo[ni][1]);
#pragma unroll
                for (int mi = 0; mi < 2; mi++)
#pragma unroll
                    for (int ni = 0; ni < 4; ni++)
                        mma16816(acc[mi][ni], wlo[mi], hhi[ni][0], hhi[ni][1]);
            }
            __syncthreads();   // buffer reads done before next overwrite
        }

        // ---- partials to smem: pbuf[w][gatecol][batch] ----
#pragma unroll
        for (int mi = 0; mi < 2; mi++) {
            int row0 = mi * 16 + (lane >> 2);
#pragma unroll
            for (int ni = 0; ni < 4; ni++) {
                int col0 = ni * 8 + (lane & 3) * 2;
                float* pb = pbuf + w * (32 * PSTR);
                *(float2*)&pb[row0 * PSTR + col0] =
                    make_float2(acc[mi][ni][0], acc[mi][ni][1]);
                *(float2*)&pb[(row0 + 8) * PSTR + col0] =
                    make_float2(acc[mi][ni][2], acc[mi][ni][3]);
            }
        }
        __syncthreads();

        // ---- reduce 8 partials + gate math (warp = cc, lane = bb) ----
        {
            const int cc = w, bb = lane;
            float pre0 = gxr0, pre1 = gxr1, pre2 = gxr2;
#pragma unroll
            for (int u = 0; u < 8; u++) {
                const float* pb = pbuf + u * (32 * PSTR) + bb;
                pre0 += pb[(cc)      * PSTR];
                pre1 += pb[(8 + cc)  * PSTR];
                pre2 += pb[(16 + cc) * PSTR];
            }
            float f  = sigm_f(pre0);
            float o  = sigm_f(pre1);
            float ch = tanh_f(pre2);
            float cold = csm[cc * 32 + bb];
            float cn = f * (cold - ch) + ch;
            float hn = o * tanh_f(cn);
            csm[cc * 32 + bb] = cn;
            tbuf[bb * 9 + cc] = hn;

            int colg = c0col + cc;
            out[((size_t)bb * S_DIM + t) * H_DIM + colg] = hn;
            if (t == S_DIM - 1 && wantTail) {
                size_t base2 = (size_t)B_DIM * S_DIM * H_DIM;
                out[base2 + (size_t)bb * H_DIM + colg] = hn;
                out[base2 + (size_t)B_DIM * H_DIM + (size_t)bb * H_DIM + colg] = cn;
            }
        }
        __syncthreads();

        // ---- h -> bf16 hi/lo, coalesced store to next epoch ----
        {
            int bb = tid >> 3, cc = tid & 7;
            float v = tbuf[bb * 9 + cc];
            __nv_bfloat16 hh = __float2bfloat16(v);
            __nv_bfloat16 hl = __float2bfloat16(v - __bfloat162float(hh));
            unsigned short uh = *(unsigned short*)&hh;
            unsigned short ul = *(unsigned short*)&hl;
            size_t go = (size_t)bb * H_DIM + c0col + cc;
            asm volatile("st.global.cg.u16 [%0], %1;"
                         :: "l"(&g_hbhi[epn][go]), "h"(uh) : "memory");
            asm volatile("st.global.cg.u16 [%0], %1;"
                         :: "l"(&g_hblo[epn][go]), "h"(ul) : "memory");
        }

        // ---- arrive (no wait): publish this CTA's step-t completion ----
        if (t < S_DIM - 1) {
            __syncthreads();
            if (tid == 0) {
                __threadfence();
                atomicAdd(&g_qcnt[grp * 64], 1u);
            }
        }
    }
}

// ---------------- launch ----------------
extern "C" void kernel_launch(void* const* d_in, const int* in_sizes, int n_in,
                              void* d_out, int out_size) {
    const float* x  = (const float*)d_in[0];
    const float* h0 = (const float*)d_in[1];
    const float* c0 = (const float*)d_in[2];
    const float* Wf = (const float*)d_in[3];
    const float* bf = (const float*)d_in[4];
    const float* Wo = (const float*)d_in[5];
    const float* bo = (const float*)d_in[6];
    const float* Wc = (const float*)d_in[7];
    const float* bc = (const float*)d_in[8];
    float* out = (float*)d_out;

    cudaFuncSetAttribute(mma_gemm,
                         cudaFuncAttributeMaxDynamicSharedMemorySize, GSMEM_BYTES);
    cudaFuncSetAttribute(lstm_recurrent,
                         cudaFuncAttributeMaxDynamicSharedMemorySize, RSMEM_BYTES);

    cvt_x<<<(B_DIM * S_DIM * I_DIM + 255) / 256, 256>>>(x);
    cvt_w<<<(3 * H_DIM * I_DIM + 255) / 256, 256>>>(Wf, Wo, Wc);
    mma_gemm<<<dim3(24, 256), 256, GSMEM_BYTES>>>(bf, bo, bc);
    init_hb<<<(B_DIM * H_DIM + 255) / 256, 256>>>(h0);
    lstm_recurrent<<<NB_CTA, NTH, RSMEM_BYTES>>>(Wf, Wo, Wc, c0, out, out_size);
}

// round 16
// speedup vs baseline: 1.1305x; 1.0934x over previous
#include <cuda_runtime.h>
#include <cuda_bf16.h>
#include <cstdint>

#define B_DIM 32
#define S_DIM 1024
#define H_DIM 1024
#define I_DIM 1024
#define KW    2048

// ---------------- scratch ----------------
__device__ float g_G[(size_t)3 * S_DIM * B_DIM * H_DIM];   // [g][t][b][h]
__device__ __nv_bfloat16 g_hbhi[2][B_DIM * H_DIM];         // h bf16 hi, [b][h]
__device__ __nv_bfloat16 g_hblo[2][B_DIM * H_DIM];         // h bf16 lo, [b][h]
__device__ unsigned g_barCount = 0;
__device__ unsigned g_barGen   = 0;
__device__ __nv_bfloat16 g_xhi[(size_t)B_DIM * S_DIM * I_DIM];
__device__ __nv_bfloat16 g_xlo[(size_t)B_DIM * S_DIM * I_DIM];
__device__ __nv_bfloat16 g_whi[(size_t)3 * H_DIM * I_DIM]; // rows g*1024+h, k<1024
__device__ __nv_bfloat16 g_wlo[(size_t)3 * H_DIM * I_DIM];

// ---------------- helpers ----------------
__device__ __forceinline__ uint32_t smem_u32(const void* p) {
    uint32_t a;
    asm("{ .reg .u64 t; cvta.to.shared.u64 t, %1; cvt.u32.u64 %0, t; }"
        : "=r"(a) : "l"(p));
    return a;
}
__device__ __forceinline__ void cpasync16(uint32_t s, const void* g) {
    asm volatile("cp.async.cg.shared.global [%0], [%1], 16;" :: "r"(s), "l"(g));
}
#define CP_COMMIT() asm volatile("cp.async.commit_group;" ::: "memory")
#define CP_WAIT1()  asm volatile("cp.async.wait_group 1;" ::: "memory")
#define CP_WAIT0()  asm volatile("cp.async.wait_group 0;" ::: "memory")

__device__ __forceinline__ void ldsm_x4(uint32_t& r0, uint32_t& r1,
                                        uint32_t& r2, uint32_t& r3,
                                        uint32_t addr) {
    asm volatile("ldmatrix.sync.aligned.m8n8.x4.shared.b16 {%0,%1,%2,%3}, [%4];"
                 : "=r"(r0), "=r"(r1), "=r"(r2), "=r"(r3) : "r"(addr));
}
__device__ __forceinline__ void ldsm_x2(uint32_t& r0, uint32_t& r1,
                                        uint32_t addr) {
    asm volatile("ldmatrix.sync.aligned.m8n8.x2.shared.b16 {%0,%1}, [%2];"
                 : "=r"(r0), "=r"(r1) : "r"(addr));
}
__device__ __forceinline__ void mma16816(float* d, const uint32_t* a,
                                         uint32_t b0, uint32_t b1) {
    asm volatile("mma.sync.aligned.m16n8k16.row.col.f32.bf16.bf16.f32 "
                 "{%0,%1,%2,%3}, {%4,%5,%6,%7}, {%8,%9}, {%0,%1,%2,%3};"
                 : "+f"(d[0]), "+f"(d[1]), "+f"(d[2]), "+f"(d[3])
                 : "r"(a[0]), "r"(a[1]), "r"(a[2]), "r"(a[3]),
                   "r"(b0), "r"(b1));
}

// ---------------- conversion kernels ----------------
__global__ void cvt_x(const float* __restrict__ x) {
    size_t i = (size_t)blockIdx.x * blockDim.x + threadIdx.x;
    if (i < (size_t)B_DIM * S_DIM * I_DIM) {
        float v = x[i];
        __nv_bfloat16 h = __float2bfloat16(v);
        g_xhi[i] = h;
        g_xlo[i] = __float2bfloat16(v - __bfloat162float(h));
    }
}
__global__ void cvt_w(const float* __restrict__ Wf, const float* __restrict__ Wo,
                      const float* __restrict__ Wc) {
    size_t i = (size_t)blockIdx.x * blockDim.x + threadIdx.x;
    if (i < (size_t)3 * H_DIM * I_DIM) {
        int g = (int)(i / (H_DIM * I_DIM));
        size_t rem = i - (size_t)g * H_DIM * I_DIM;
        int h = (int)(rem >> 10), k = (int)(rem & 1023);
        const float* W = (g == 0) ? Wf : (g == 1 ? Wo : Wc);
        float v = W[(size_t)h * KW + k];
        __nv_bfloat16 hh = __float2bfloat16(v);
        g_whi[i] = hh;
        g_wlo[i] = __float2bfloat16(v - __bfloat162float(hh));
    }
}

// ---------------- Phase 1: mma.sync bf16 GEMM (3-term hi/lo), proven ----------------
#define APAD 40
#define ALO_OFF 5120
#define BHI_OFF 10240
#define BLO_OFF 15360
#define STG_ELEMS 20480
#define GSMEM_BYTES (2 * STG_ELEMS * 2)

extern __shared__ __nv_bfloat16 g_sm[];

__global__ __launch_bounds__(256, 1)
void mma_gemm(const float* __restrict__ bf, const float* __restrict__ bo,
              const float* __restrict__ bc) {
    uint32_t sbase = smem_u32(g_sm);
    const int tid = threadIdx.x, lane = tid & 31, warp = tid >> 5;
    const int wm = warp & 1, wn = warp >> 1;
    const int g  = blockIdx.x >> 3;
    const int h0 = (blockIdx.x & 7) * 128;
    const int rowBase = blockIdx.y * 128;
    const size_t aG = (size_t)rowBase * 1024;
    const size_t bG = ((size_t)g * 1024 + h0) * 1024;

    auto loadStage = [&](int st, int kt) {
        uint32_t sb = sbase + st * (STG_ELEMS * 2);
        for (int i = tid; i < 512; i += 256) {
            int r = i >> 2, c = i & 3;
            uint32_t off = (uint32_t)(r * APAD + c * 8) * 2;
            size_t src = (size_t)r * 1024 + kt + c * 8;
            cpasync16(sb + off,               g_xhi + aG + src);
            cpasync16(sb + ALO_OFF * 2 + off, g_xlo + aG + src);
            cpasync16(sb + BHI_OFF * 2 + off, g_whi + bG + src);
            cpasync16(sb + BLO_OFF * 2 + off, g_wlo + bG + src);
        }
    };

    float acc[4][4][4];
#pragma unroll
    for (int mi = 0; mi < 4; mi++)
#pragma unroll
        for (int ni = 0; ni < 4; ni++)
#pragma unroll
            for (int u = 0; u < 4; u++) acc[mi][ni][u] = 0.f;

    loadStage(0, 0);  CP_COMMIT();
    loadStage(1, 32); CP_COMMIT();

    const int aRow = wm * 64 + (lane & 15);
    const int aColB = (lane >> 4) * 16;
    const int bRow = wn * 32 + (lane & 7) + ((lane >> 4) << 3);
    const int bColB = ((lane >> 3) & 1) * 16;

    for (int kt = 0; kt < 32; kt++) {
        CP_WAIT1();
        __syncthreads();
        uint32_t sb = sbase + (kt & 1) * (STG_ELEMS * 2);
#pragma unroll
        for (int kk = 0; kk < 2; kk++) {
            uint32_t ahi[4][4], alo[4][4];
#pragma unroll
            for (int mi = 0; mi < 4; mi++) {
                uint32_t ad = sb + (uint32_t)((aRow + mi * 16) * APAD) * 2
                            + kk * 32 + aColB;
                ldsm_x4(ahi[mi][0], ahi[mi][1], ahi[mi][2], ahi[mi][3], ad);
                ldsm_x4(alo[mi][0], alo[mi][1], alo[mi][2], alo[mi][3],
                        ad + ALO_OFF * 2);
            }
            uint32_t bhi[4][2], blo[4][2];
#pragma unroll
            for (int nh = 0; nh < 2; nh++) {
                uint32_t bd = sb + BHI_OFF * 2
                            + (uint32_t)((bRow + nh * 16) * APAD) * 2
                            + kk * 32 + bColB;
                uint32_t r0, r1, r2, r3;
                ldsm_x4(r0, r1, r2, r3, bd);
                bhi[nh * 2][0] = r0; bhi[nh * 2][1] = r1;
                bhi[nh * 2 + 1][0] = r2; bhi[nh * 2 + 1][1] = r3;
                ldsm_x4(r0, r1, r2, r3, bd + (BLO_OFF - BHI_OFF) * 2);
                blo[nh * 2][0] = r0; blo[nh * 2][1] = r1;
                blo[nh * 2 + 1][0] = r2; blo[nh * 2 + 1][1] = r3;
            }
#pragma unroll
            for (int mi = 0; mi < 4; mi++)
#pragma unroll
                for (int ni = 0; ni < 4; ni++) {
                    mma16816(acc[mi][ni], ahi[mi], bhi[ni][0], bhi[ni][1]);
                    mma16816(acc[mi][ni], ahi[mi], blo[ni][0], blo[ni][1]);
                    mma16816(acc[mi][ni], alo[mi], bhi[ni][0], bhi[ni][1]);
                }
        }
        __syncthreads();
        if (kt + 2 < 32) loadStage(kt & 1, (kt + 2) * 32);
        CP_COMMIT();
    }

    const float* bias = (g == 0) ? bf : (g == 1 ? bo : bc);
    const int b    = rowBase >> 10;
    const int tLoc = rowBase & 1023;
#pragma unroll
    for (int ni = 0; ni < 4; ni++) {
        int h = h0 + wn * 32 + ni * 8 + (lane & 3) * 2;
        float bx = __ldg(&bias[h]), by = __ldg(&bias[h + 1]);
#pragma unroll
        for (int mi = 0; mi < 4; mi++) {
            int t0 = tLoc + wm * 64 + mi * 16 + (lane >> 2);
            float2 v0 = make_float2(acc[mi][ni][0] + bx, acc[mi][ni][1] + by);
            float2 v1 = make_float2(acc[mi][ni][2] + bx, acc[mi][ni][3] + by);
            *(float2*)&g_G[(((size_t)g * S_DIM + t0) * B_DIM + b) * H_DIM + h] = v0;
            *(float2*)&g_G[(((size_t)g * S_DIM + t0 + 8) * B_DIM + b) * H_DIM + h] = v1;
        }
    }
}

// ---------------- init h0 -> bf16 hi/lo [b][h] ----------------
__global__ void init_hb(const float* __restrict__ h0) {
    int i = blockIdx.x * blockDim.x + threadIdx.x;
    if (i < B_DIM * H_DIM) {
        float v = h0[i];
        __nv_bfloat16 hh = __float2bfloat16(v);
        g_hbhi[0][i] = hh;
        g_hblo[0][i] = __float2bfloat16(v - __bfloat162float(hh));
    }
}

// ---------------- Phase 2: persistent recurrence (tensor dot, pipelined) ----------------
#define NB_CTA 128
#define CPB    8
#define NTH    256
// smem byte offsets
#define SW_HI   0u
#define SW_LO   66048u          // 32 rows * 2064 B
#define SH_BASE 132096u         // 2 buffers x (hi 16896 + lo 16896)
#define HBUFSZ  33792u
#define HLO_OFF 16896u
#define PBUF_B  132096u         // alias over h buffers (dead at partials time)
#define CSM_B   199680u
#define TBUF_B  200704u
#define RSMEM_BYTES 201856u
#define WSTRB   2064            // sW row stride bytes (1032 bf16)
#define HSTRB   528             // sH quarter row stride bytes (264 bf16)
#define PSTR    34              // pbuf row stride floats

__device__ __forceinline__ void gridSync(unsigned nb) {
    __syncthreads();
    if (threadIdx.x == 0) {
        __threadfence();
        unsigned gen = *(volatile unsigned*)&g_barGen;
        if (atomicAdd(&g_barCount, 1u) == nb - 1u) {
            *(volatile unsigned*)&g_barCount = 0u;
            __threadfence();
            *(volatile unsigned*)&g_barGen = gen + 1u;
        } else {
            while (*(volatile unsigned*)&g_barGen == gen) { __nanosleep(20); }
        }
        __threadfence();
    }
    __syncthreads();
}
__device__ __forceinline__ float sigm_f(float x) {
    return __fdividef(1.f, 1.f + __expf(-x));
}
__device__ __forceinline__ float tanh_f(float x) {
    return 1.f - __fdividef(2.f, 1.f + __expf(2.f * x));
}

extern __shared__ char r_sm[];

__global__ __launch_bounds__(NTH, 1)
void lstm_recurrent(const float* __restrict__ Wf, const float* __restrict__ Wo,
                    const float* __restrict__ Wc, const float* __restrict__ c0,
                    float* __restrict__ out, int out_size) {
    const uint32_t sA = smem_u32(r_sm);
    float* csm  = (float*)(r_sm + CSM_B);     // [cc*32 + bb]
    float* tbuf = (float*)(r_sm + TBUF_B);    // [bb*9 + cc]
    float* pbuf = (float*)(r_sm + PBUF_B);    // [w][gatecol(34)][batch]

    const int tid  = threadIdx.x;
    const int bid  = blockIdx.x;
    const int c0col = bid * CPB;
    const int lane = tid & 31;
    const int w    = tid >> 5;                // 8 warps
    const unsigned nb = gridDim.x;

    // ---- one-time: recurrent weights fp32 -> bf16 hi/lo into smem ----
    for (int i = tid; i < 24 * 1024; i += NTH) {
        int row = i >> 10, k = i & 1023;
        int gg = row >> 3, cc = row & 7;
        const float* Wsel = (gg == 0) ? Wf : (gg == 1 ? Wo : Wc);
        float v = Wsel[(size_t)(c0col + cc) * KW + I_DIM + k];
        __nv_bfloat16 hh = __float2bfloat16(v);
        __nv_bfloat16 hl = __float2bfloat16(v - __bfloat162float(hh));
        *(__nv_bfloat16*)(r_sm + SW_HI + row * WSTRB + k * 2) = hh;
        *(__nv_bfloat16*)(r_sm + SW_LO + row * WSTRB + k * 2) = hl;
    }
    for (int i = tid; i < 8 * (WSTRB / 4); i += NTH) {
        int row = 24 + i / (WSTRB / 4), wd = i % (WSTRB / 4);
        *(uint32_t*)(r_sm + SW_HI + row * WSTRB + wd * 4) = 0u;
        *(uint32_t*)(r_sm + SW_LO + row * WSTRB + wd * 4) = 0u;
    }
    for (int i = tid; i < B_DIM * CPB; i += NTH) {
        int cc = i >> 5, bb = i & 31;
        csm[cc * 32 + bb] = c0[bb * H_DIM + c0col + cc];
    }
    __syncthreads();

    const bool wantTail = (out_size >= (B_DIM * S_DIM * H_DIM + 2 * B_DIM * H_DIM));

    // ldmatrix lane addressing — A pattern on h (rows=batch), B pattern on W
    const int aRB = (lane & 15) * HSTRB + ((lane >> 4) << 4);             // h
    const int bRB4 = ((lane & 7) + ((lane >> 4) << 3)) * WSTRB
                   + (((lane >> 3) & 1) << 4);                            // W rows 0-15
    const int bRB2 = (16 + (lane & 7)) * WSTRB + (((lane >> 3) & 1) << 4); // W rows 16-23

    for (int t = 0; t < S_DIM; t++) {
        const int ep = t & 1, epn = ep ^ 1;
        const __nv_bfloat16* hhiG = g_hbhi[ep];
        const __nv_bfloat16* hloG = g_hblo[ep];

        // stage one K-quarter (256 k) of h hi/lo into buffer `buf`
        auto stageQ = [&](int q, int buf) {
            const uint32_t dst = sA + SH_BASE + (uint32_t)buf * HBUFSZ;
            for (int i = tid; i < 1024; i += NTH) {
                int row = i >> 5, c = i & 31;
                size_t gsrc = (size_t)row * 1024 + q * 256 + c * 8;
                uint32_t o = (uint32_t)(row * HSTRB + c * 16);
                cpasync16(dst + o,           hhiG + gsrc);
                cpasync16(dst + HLO_OFF + o, hloG + gsrc);
            }
        };

        // prefetch x-part pre-activations (warp -> cc, lane -> bb)
        float gxr0, gxr1, gxr2;
        {
            size_t ofs = ((size_t)t * B_DIM + lane) * H_DIM + c0col + w;
            const size_t GSTR = (size_t)S_DIM * B_DIM * H_DIM;
            gxr0 = __ldg(&g_G[ofs]);
            gxr1 = __ldg(&g_G[GSTR + ofs]);
            gxr2 = __ldg(&g_G[2 * GSTR + ofs]);
        }

        float acc[2][3][4];
#pragma unroll
        for (int mi = 0; mi < 2; mi++)
#pragma unroll
            for (int ni = 0; ni < 3; ni++)
#pragma unroll
                for (int u = 0; u < 4; u++) acc[mi][ni][u] = 0.f;

        stageQ(0, 0); CP_COMMIT();

#pragma unroll
        for (int q = 0; q < 4; q++) {
            if (q < 3) { stageQ(q + 1, (q + 1) & 1); CP_COMMIT(); CP_WAIT1(); }
            else       { CP_WAIT0(); }
            __syncthreads();

            const uint32_t hb = sA + SH_BASE + (uint32_t)(q & 1) * HBUFSZ;
#pragma unroll
            for (int kk = 0; kk < 2; kk++) {
                const uint32_t colWb = (uint32_t)(q * 16 + w * 2 + kk) * 32;
                const uint32_t colHb = (uint32_t)(w * 2 + kk) * 32;

                // A = h fragments (rows = batches), 2 m16 tiles, hi+lo
                uint32_t hhi[2][4], hlo[2][4];
#pragma unroll
                for (int mi = 0; mi < 2; mi++) {
                    uint32_t ad = hb + (uint32_t)(mi * 16 * HSTRB) + aRB + colHb;
                    ldsm_x4(hhi[mi][0], hhi[mi][1], hhi[mi][2], hhi[mi][3], ad);
                    ldsm_x4(hlo[mi][0], hlo[mi][1], hlo[mi][2], hlo[mi][3],
                            ad + HLO_OFF);
                }
                // B = W fragments (rows = gatecols), 3 n8 tiles, hi+lo
                uint32_t whi[3][2], wlo[3][2];
                {
                    uint32_t bd = sA + SW_HI + bRB4 + colWb;
                    uint32_t r0, r1, r2, r3;
                    ldsm_x4(r0, r1, r2, r3, bd);
                    whi[0][0] = r0; whi[0][1] = r1;
                    whi[1][0] = r2; whi[1][1] = r3;
                    ldsm_x4(r0, r1, r2, r3, bd + (SW_LO - SW_HI));
                    wlo[0][0] = r0; wlo[0][1] = r1;
                    wlo[1][0] = r2; wlo[1][1] = r3;
                    uint32_t bd2 = sA + SW_HI + bRB2 + colWb;
                    ldsm_x2(whi[2][0], whi[2][1], bd2);
                    ldsm_x2(wlo[2][0], wlo[2][1], bd2 + (SW_LO - SW_HI));
                }
#pragma unroll
                for (int mi = 0; mi < 2; mi++)
#pragma unroll
                    for (int ni = 0; ni < 3; ni++)
                        mma16816(acc[mi][ni], hhi[mi], whi[ni][0], whi[ni][1]);
#pragma unroll
                for (int mi = 0; mi < 2; mi++)
#pragma unroll
                    for (int ni = 0; ni < 3; ni++)
                        mma16816(acc[mi][ni], hlo[mi], whi[ni][0], whi[ni][1]);
#pragma unroll
                for (int mi = 0; mi < 2; mi++)
#pragma unroll
                    for (int ni = 0; ni < 3; ni++)
                        mma16816(acc[mi][ni], hhi[mi], wlo[ni][0], wlo[ni][1]);
            }
            __syncthreads();   // buffer reads done before next overwrite
        }

        // ---- partials to smem (transposed): pbuf[w][gatecol][batch] ----
#pragma unroll
        for (int mi = 0; mi < 2; mi++) {
            int rb = mi * 16 + (lane >> 2);          // batch
#pragma unroll
            for (int ni = 0; ni < 3; ni++) {
                int cg = ni * 8 + (lane & 3) * 2;    // gatecol
                float* pb = pbuf + w * (32 * PSTR);
                pb[cg * PSTR + rb]           = acc[mi][ni][0];
                pb[(cg + 1) * PSTR + rb]     = acc[mi][ni][1];
                pb[cg * PSTR + rb + 8]       = acc[mi][ni][2];
                pb[(cg + 1) * PSTR + rb + 8] = acc[mi][ni][3];
            }
        }
        __syncthreads();

        // ---- reduce 8 partials + gate math (warp = cc, lane = bb) ----
        {
            const int cc = w, bb = lane;
            float pre0 = gxr0, pre1 = gxr1, pre2 = gxr2;
#pragma unroll
            for (int u = 0; u < 8; u++) {
                const float* pb = pbuf + u * (32 * PSTR) + bb;
                pre0 += pb[(cc)      * PSTR];
                pre1 += pb[(8 + cc)  * PSTR];
                pre2 += pb[(16 + cc) * PSTR];
            }
            float f  = sigm_f(pre0);
            float o  = sigm_f(pre1);
            float ch = tanh_f(pre2);
            float cold = csm[cc * 32 + bb];
            float cn = f * (cold - ch) + ch;
            float hn = o * tanh_f(cn);
            csm[cc * 32 + bb] = cn;
            tbuf[bb * 9 + cc] = hn;

            int colg = c0col + cc;
            out[((size_t)bb * S_DIM + t) * H_DIM + colg] = hn;
            if (t == S_DIM - 1 && wantTail) {
                size_t base2 = (size_t)B_DIM * S_DIM * H_DIM;
                out[base2 + (size_t)bb * H_DIM + colg] = hn;
                out[base2 + (size_t)B_DIM * H_DIM + (size_t)bb * H_DIM + colg] = cn;
            }
        }
        __syncthreads();

        // ---- h -> bf16 hi/lo, coalesced store to next epoch ----
        {
            int bb = tid >> 3, cc = tid & 7;
            float v = tbuf[bb * 9 + cc];
            __nv_bfloat16 hh = __float2bfloat16(v);
            __nv_bfloat16 hl = __float2bfloat16(v - __bfloat162float(hh));
            unsigned short uh = *(unsigned short*)&hh;
            unsigned short ul = *(unsigned short*)&hl;
            size_t go = (size_t)bb * H_DIM + c0col + cc;
            asm volatile("st.global.cg.u16 [%0], %1;"
                         :: "l"(&g_hbhi[epn][go]), "h"(uh) : "memory");
            asm volatile("st.global.cg.u16 [%0], %1;"
                         :: "l"(&g_hblo[epn][go]), "h"(ul) : "memory");
        }

        if (t < S_DIM - 1) gridSync(nb);
    }
}

// ---------------- launch ----------------
extern "C" void kernel_launch(void* const* d_in, const int* in_sizes, int n_in,
                              void* d_out, int out_size) {
    const float* x  = (const float*)d_in[0];
    const float* h0 = (const float*)d_in[1];
    const float* c0 = (const float*)d_in[2];
    const float* Wf = (const float*)d_in[3];
    const float* bf = (const float*)d_in[4];
    const float* Wo = (const float*)d_in[5];
    const float* bo = (const float*)d_in[6];
    const float* Wc = (const float*)d_in[7];
    const float* bc = (const float*)d_in[8];
    float* out = (float*)d_out;

    cudaFuncSetAttribute(mma_gemm,
                         cudaFuncAttributeMaxDynamicSharedMemorySize, GSMEM_BYTES);
    cudaFuncSetAttribute(lstm_recurrent,
                         cudaFuncAttributeMaxDynamicSharedMemorySize, RSMEM_BYTES);

    cvt_x<<<(B_DIM * S_DIM * I_DIM + 255) / 256, 256>>>(x);
    cvt_w<<<(3 * H_DIM * I_DIM + 255) / 256, 256>>>(Wf, Wo, Wc);
    mma_gemm<<<dim3(24, 256), 256, GSMEM_BYTES>>>(bf, bo, bc);
    init_hb<<<(B_DIM * H_DIM + 255) / 256, 256>>>(h0);
    lstm_recurrent<<<NB_CTA, NTH, RSMEM_BYTES>>>(Wf, Wo, Wc, c0, out, out_size);
}

// round 17
// speedup vs baseline: 1.1610x; 1.0270x over previous
#include <cuda_runtime.h>
#include <cuda_bf16.h>
#include <cstdint>

#define B_DIM 32
#define S_DIM 1024
#define H_DIM 1024
#define I_DIM 1024
#define KW    2048

// ---------------- scratch ----------------
__device__ float g_G[(size_t)3 * S_DIM * B_DIM * H_DIM];   // [g][t][b][h]
__device__ __nv_bfloat16 g_hbhi[2][B_DIM * H_DIM];         // h bf16 hi, [b][h]
__device__ __nv_bfloat16 g_hblo[2][B_DIM * H_DIM];         // h bf16 lo, [b][h]
__device__ unsigned g_barCount = 0;
__device__ unsigned g_barGen   = 0;
__device__ __nv_bfloat16 g_xhi[(size_t)B_DIM * S_DIM * I_DIM];
__device__ __nv_bfloat16 g_xlo[(size_t)B_DIM * S_DIM * I_DIM];
__device__ __nv_bfloat16 g_whi[(size_t)3 * H_DIM * I_DIM]; // rows g*1024+h, k<1024
__device__ __nv_bfloat16 g_wlo[(size_t)3 * H_DIM * I_DIM];

// ---------------- helpers ----------------
__device__ __forceinline__ uint32_t smem_u32(const void* p) {
    uint32_t a;
    asm("{ .reg .u64 t; cvta.to.shared.u64 t, %1; cvt.u32.u64 %0, t; }"
        : "=r"(a) : "l"(p));
    return a;
}
__device__ __forceinline__ void cpasync16(uint32_t s, const void* g) {
    asm volatile("cp.async.cg.shared.global [%0], [%1], 16;" :: "r"(s), "l"(g));
}
#define CP_COMMIT() asm volatile("cp.async.commit_group;" ::: "memory")
#define CP_WAIT1()  asm volatile("cp.async.wait_group 1;" ::: "memory")
#define CP_WAIT0()  asm volatile("cp.async.wait_group 0;" ::: "memory")

__device__ __forceinline__ void ldsm_x4(uint32_t& r0, uint32_t& r1,
                                        uint32_t& r2, uint32_t& r3,
                                        uint32_t addr) {
    asm volatile("ldmatrix.sync.aligned.m8n8.x4.shared.b16 {%0,%1,%2,%3}, [%4];"
                 : "=r"(r0), "=r"(r1), "=r"(r2), "=r"(r3) : "r"(addr));
}
__device__ __forceinline__ void mma16816(float* d, const uint32_t* a,
                                         uint32_t b0, uint32_t b1) {
    asm volatile("mma.sync.aligned.m16n8k16.row.col.f32.bf16.bf16.f32 "
                 "{%0,%1,%2,%3}, {%4,%5,%6,%7}, {%8,%9}, {%0,%1,%2,%3};"
                 : "+f"(d[0]), "+f"(d[1]), "+f"(d[2]), "+f"(d[3])
                 : "r"(a[0]), "r"(a[1]), "r"(a[2]), "r"(a[3]),
                   "r"(b0), "r"(b1));
}

// ---------------- conversion kernels ----------------
__global__ void cvt_x(const float* __restrict__ x) {
    size_t i = (size_t)blockIdx.x * blockDim.x + threadIdx.x;
    if (i < (size_t)B_DIM * S_DIM * I_DIM) {
        float v = x[i];
        __nv_bfloat16 h = __float2bfloat16(v);
        g_xhi[i] = h;
        g_xlo[i] = __float2bfloat16(v - __bfloat162float(h));
    }
}
__global__ void cvt_w(const float* __restrict__ Wf, const float* __restrict__ Wo,
                      const float* __restrict__ Wc) {
    size_t i = (size_t)blockIdx.x * blockDim.x + threadIdx.x;
    if (i < (size_t)3 * H_DIM * I_DIM) {
        int g = (int)(i / (H_DIM * I_DIM));
        size_t rem = i - (size_t)g * H_DIM * I_DIM;
        int h = (int)(rem >> 10), k = (int)(rem & 1023);
        const float* W = (g == 0) ? Wf : (g == 1 ? Wo : Wc);
        float v = W[(size_t)h * KW + k];
        __nv_bfloat16 hh = __float2bfloat16(v);
        g_whi[i] = hh;
        g_wlo[i] = __float2bfloat16(v - __bfloat162float(hh));
    }
}

// ---------------- Phase 1: mma.sync bf16 GEMM (3-term hi/lo), proven ----------------
#define APAD 40
#define ALO_OFF 5120
#define BHI_OFF 10240
#define BLO_OFF 15360
#define STG_ELEMS 20480
#define GSMEM_BYTES (2 * STG_ELEMS * 2)

extern __shared__ __nv_bfloat16 g_sm[];

__global__ __launch_bounds__(256, 2)
void mma_gemm(const float* __restrict__ bf, const float* __restrict__ bo,
              const float* __restrict__ bc) {
    uint32_t sbase = smem_u32(g_sm);
    const int tid = threadIdx.x, lane = tid & 31, warp = tid >> 5;
    const int wm = warp & 1, wn = warp >> 1;
    const int g  = blockIdx.x >> 3;
    const int h0 = (blockIdx.x & 7) * 128;
    const int rowBase = blockIdx.y * 128;
    const size_t aG = (size_t)rowBase * 1024;
    const size_t bG = ((size_t)g * 1024 + h0) * 1024;

    auto loadStage = [&](int st, int kt) {
        uint32_t sb = sbase + st * (STG_ELEMS * 2);
        for (int i = tid; i < 512; i += 256) {
            int r = i >> 2, c = i & 3;
            uint32_t off = (uint32_t)(r * APAD + c * 8) * 2;
            size_t src = (size_t)r * 1024 + kt + c * 8;
            cpasync16(sb + off,               g_xhi + aG + src);
            cpasync16(sb + ALO_OFF * 2 + off, g_xlo + aG + src);
            cpasync16(sb + BHI_OFF * 2 + off, g_whi + bG + src);
            cpasync16(sb + BLO_OFF * 2 + off, g_wlo + bG + src);
        }
    };

    float acc[4][4][4];
#pragma unroll
    for (int mi = 0; mi < 4; mi++)
#pragma unroll
        for (int ni = 0; ni < 4; ni++)
#pragma unroll
            for (int u = 0; u < 4; u++) acc[mi][ni][u] = 0.f;

    loadStage(0, 0);  CP_COMMIT();
    loadStage(1, 32); CP_COMMIT();

    const int aRow = wm * 64 + (lane & 15);
    const int aColB = (lane >> 4) * 16;
    const int bRow = wn * 32 + (lane & 7) + ((lane >> 4) << 3);
    const int bColB = ((lane >> 3) & 1) * 16;

    for (int kt = 0; kt < 32; kt++) {
        CP_WAIT1();
        __syncthreads();
        uint32_t sb = sbase + (kt & 1) * (STG_ELEMS * 2);
#pragma unroll
        for (int kk = 0; kk < 2; kk++) {
            uint32_t ahi[4][4], alo[4][4];
#pragma unroll
            for (int mi = 0; mi < 4; mi++) {
                uint32_t ad = sb + (uint32_t)((aRow + mi * 16) * APAD) * 2
                            + kk * 32 + aColB;
                ldsm_x4(ahi[mi][0], ahi[mi][1], ahi[mi][2], ahi[mi][3], ad);
                ldsm_x4(alo[mi][0], alo[mi][1], alo[mi][2], alo[mi][3],
                        ad + ALO_OFF * 2);
            }
            uint32_t bhi[4][2], blo[4][2];
#pragma unroll
            for (int nh = 0; nh < 2; nh++) {
                uint32_t bd = sb + BHI_OFF * 2
                            + (uint32_t)((bRow + nh * 16) * APAD) * 2
                            + kk * 32 + bColB;
                uint32_t r0, r1, r2, r3;
                ldsm_x4(r0, r1, r2, r3, bd);
                bhi[nh * 2][0] = r0; bhi[nh * 2][1] = r1;
                bhi[nh * 2 + 1][0] = r2; bhi[nh * 2 + 1][1] = r3;
                ldsm_x4(r0, r1, r2, r3, bd + (BLO_OFF - BHI_OFF) * 2);
                blo[nh * 2][0] = r0; blo[nh * 2][1] = r1;
                blo[nh * 2 + 1][0] = r2; blo[nh * 2 + 1][1] = r3;
            }
#pragma unroll
            for (int mi = 0; mi < 4; mi++)
#pragma unroll
                for (int ni = 0; ni < 4; ni++) {
                    mma16816(acc[mi][ni], ahi[mi], bhi[ni][0], bhi[ni][1]);
                    mma16816(acc[mi][ni], ahi[mi], blo[ni][0], blo[ni][1]);
                    mma16816(acc[mi][ni], alo[mi], bhi[ni][0], bhi[ni][1]);
                }
        }
        __syncthreads();
        if (kt + 2 < 32) loadStage(kt & 1, (kt + 2) * 32);
        CP_COMMIT();
    }

    const float* bias = (g == 0) ? bf : (g == 1 ? bo : bc);
    const int b    = rowBase >> 10;
    const int tLoc = rowBase & 1023;
#pragma unroll
    for (int ni = 0; ni < 4; ni++) {
        int h = h0 + wn * 32 + ni * 8 + (lane & 3) * 2;
        float bx = __ldg(&bias[h]), by = __ldg(&bias[h + 1]);
#pragma unroll
        for (int mi = 0; mi < 4; mi++) {
            int t0 = tLoc + wm * 64 + mi * 16 + (lane >> 2);
            float2 v0 = make_float2(acc[mi][ni][0] + bx, acc[mi][ni][1] + by);
            float2 v1 = make_float2(acc[mi][ni][2] + bx, acc[mi][ni][3] + by);
            *(float2*)&g_G[(((size_t)g * S_DIM + t0) * B_DIM + b) * H_DIM + h] = v0;
            *(float2*)&g_G[(((size_t)g * S_DIM + t0 + 8) * B_DIM + b) * H_DIM + h] = v1;
        }
    }
}

// ---------------- init h0 -> bf16 hi/lo [b][h] ----------------
__global__ void init_hb(const float* __restrict__ h0) {
    int i = blockIdx.x * blockDim.x + threadIdx.x;
    if (i < B_DIM * H_DIM) {
        float v = h0[i];
        __nv_bfloat16 hh = __float2bfloat16(v);
        g_hbhi[0][i] = hh;
        g_hblo[0][i] = __float2bfloat16(v - __bfloat162float(hh));
    }
}

// ---------------- Phase 2: persistent recurrence (tensor dot, 3-buf pipeline) ----------------
#define NB_CTA 128
#define CPB    8
#define NTH    256
// smem byte offsets (sW now 24 rows only — padding rows never read after op swap)
#define SW_HI   0u
#define SW_LO   49536u          // 24 rows * 2064 B
#define SH_BASE 99072u          // 3 buffers x (hi 16896 + lo 16896)
#define HBUFSZ  33792u
#define HLO_OFF 16896u
#define PBUF_B  99072u          // alias over h buffers (dead at partials time)
#define CSM_B   200448u
#define TBUF_B  201472u
#define RSMEM_BYTES 202624u
#define WSTRB   2064            // sW row stride bytes (1032 bf16)
#define HSTRB   528             // sH quarter row stride bytes (264 bf16)
#define PSTR    34              // pbuf row stride floats

__device__ __forceinline__ void gridSync(unsigned nb) {
    __syncthreads();
    if (threadIdx.x == 0) {
        __threadfence();
        unsigned gen = *(volatile unsigned*)&g_barGen;
        if (atomicAdd(&g_barCount, 1u) == nb - 1u) {
            *(volatile unsigned*)&g_barCount = 0u;
            __threadfence();
            *(volatile unsigned*)&g_barGen = gen + 1u;
        } else {
            while (*(volatile unsigned*)&g_barGen == gen) { __nanosleep(20); }
        }
        __threadfence();
    }
    __syncthreads();
}
__device__ __forceinline__ float sigm_f(float x) {
    return __fdividef(1.f, 1.f + __expf(-x));
}
__device__ __forceinline__ float tanh_f(float x) {
    return 1.f - __fdividef(2.f, 1.f + __expf(2.f * x));
}

extern __shared__ char r_sm[];

__global__ __launch_bounds__(NTH, 1)
void lstm_recurrent(const float* __restrict__ Wf, const float* __restrict__ Wo,
                    const float* __restrict__ Wc, const float* __restrict__ c0,
                    float* __restrict__ out, int out_size) {
    const uint32_t sA = smem_u32(r_sm);
    float* csm  = (float*)(r_sm + CSM_B);     // [cc*32 + bb]
    float* tbuf = (float*)(r_sm + TBUF_B);    // [bb*9 + cc]
    float* pbuf = (float*)(r_sm + PBUF_B);    // [w][gatecol(34)][batch]

    const int tid  = threadIdx.x;
    const int bid  = blockIdx.x;
    const int c0col = bid * CPB;
    const int lane = tid & 31;
    const int w    = tid >> 5;                // 8 warps
    const unsigned nb = gridDim.x;

    // ---- one-time: recurrent weights fp32 -> bf16 hi/lo into smem (24 rows) ----
    for (int i = tid; i < 24 * 1024; i += NTH) {
        int row = i >> 10, k = i & 1023;
        int gg = row >> 3, cc = row & 7;
        const float* Wsel = (gg == 0) ? Wf : (gg == 1 ? Wo : Wc);
        float v = Wsel[(size_t)(c0col + cc) * KW + I_DIM + k];
        __nv_bfloat16 hh = __float2bfloat16(v);
        __nv_bfloat16 hl = __float2bfloat16(v - __bfloat162float(hh));
        *(__nv_bfloat16*)(r_sm + SW_HI + row * WSTRB + k * 2) = hh;
        *(__nv_bfloat16*)(r_sm + SW_LO + row * WSTRB + k * 2) = hl;
    }
    for (int i = tid; i < B_DIM * CPB; i += NTH) {
        int cc = i >> 5, bb = i & 31;
        csm[cc * 32 + bb] = c0[bb * H_DIM + c0col + cc];
    }
    __syncthreads();

    const bool wantTail = (out_size >= (B_DIM * S_DIM * H_DIM + 2 * B_DIM * H_DIM));

    // ldmatrix lane addressing — A pattern on h (rows=batch), B pattern on W
    const int aRB = (lane & 15) * HSTRB + ((lane >> 4) << 4);             // h
    const int bRB4 = ((lane & 7) + ((lane >> 4) << 3)) * WSTRB
                   + (((lane >> 3) & 1) << 4);                            // W rows 0-15
    // merged hi/lo x4 for W rows 16-23: lanes 0-15 -> hi plane, 16-31 -> lo plane
    const int bRB2 = (16 + (lane & 7)) * WSTRB + (((lane >> 3) & 1) << 4)
                   + ((lane >= 16) ? (int)(SW_LO - SW_HI) : 0);

    for (int t = 0; t < S_DIM; t++) {
        const int ep = t & 1, epn = ep ^ 1;
        const __nv_bfloat16* hhiG = g_hbhi[ep];
        const __nv_bfloat16* hloG = g_hblo[ep];

        // stage one K-quarter (256 k) of h hi/lo into buffer `buf`
        auto stageQ = [&](int q, int buf) {
            const uint32_t dst = sA + SH_BASE + (uint32_t)buf * HBUFSZ;
            for (int i = tid; i < 1024; i += NTH) {
                int row = i >> 5, c = i & 31;
                size_t gsrc = (size_t)row * 1024 + q * 256 + c * 8;
                uint32_t o = (uint32_t)(row * HSTRB + c * 16);
                cpasync16(dst + o,           hhiG + gsrc);
                cpasync16(dst + HLO_OFF + o, hloG + gsrc);
            }
        };

        // prefetch x-part pre-activations (warp -> cc, lane -> bb)
        float gxr0, gxr1, gxr2;
        {
            size_t ofs = ((size_t)t * B_DIM + lane) * H_DIM + c0col + w;
            const size_t GSTR = (size_t)S_DIM * B_DIM * H_DIM;
            gxr0 = __ldg(&g_G[ofs]);
            gxr1 = __ldg(&g_G[GSTR + ofs]);
            gxr2 = __ldg(&g_G[2 * GSTR + ofs]);
        }

        float acc[2][3][4];
#pragma unroll
        for (int mi = 0; mi < 2; mi++)
#pragma unroll
            for (int ni = 0; ni < 3; ni++)
#pragma unroll
                for (int u = 0; u < 4; u++) acc[mi][ni][u] = 0.f;

        stageQ(0, 0); CP_COMMIT();

#pragma unroll
        for (int q = 0; q < 4; q++) {
            if (q < 3) { stageQ(q + 1, (q + 1) % 3); CP_COMMIT(); CP_WAIT1(); }
            else       { CP_WAIT0(); }
            __syncthreads();   // consumer sync: stage q visible to all

            const uint32_t hb = sA + SH_BASE + (uint32_t)(q % 3) * HBUFSZ;
#pragma unroll
            for (int kk = 0; kk < 2; kk++) {
                const uint32_t colWb = (uint32_t)(q * 16 + w * 2 + kk) * 32;
                const uint32_t colHb = (uint32_t)(w * 2 + kk) * 32;

                // A = h fragments (rows = batches), 2 m16 tiles, hi+lo
                uint32_t hhi[2][4], hlo[2][4];
#pragma unroll
                for (int mi = 0; mi < 2; mi++) {
                    uint32_t ad = hb + (uint32_t)(mi * 16 * HSTRB) + aRB + colHb;
                    ldsm_x4(hhi[mi][0], hhi[mi][1], hhi[mi][2], hhi[mi][3], ad);
                    ldsm_x4(hlo[mi][0], hlo[mi][1], hlo[mi][2], hlo[mi][3],
                            ad + HLO_OFF);
                }
                // B = W fragments (rows = gatecols), 3 n8 tiles, hi+lo
                uint32_t whi[3][2], wlo[3][2];
                {
                    uint32_t bd = sA + SW_HI + bRB4 + colWb;
                    uint32_t r0, r1, r2, r3;
                    ldsm_x4(r0, r1, r2, r3, bd);
                    whi[0][0] = r0; whi[0][1] = r1;
                    whi[1][0] = r2; whi[1][1] = r3;
                    ldsm_x4(r0, r1, r2, r3, bd + (SW_LO - SW_HI));
                    wlo[0][0] = r0; wlo[0][1] = r1;
                    wlo[1][0] = r2; wlo[1][1] = r3;
                    // merged: rows 16-23 hi (lanes 0-15) + lo (lanes 16-31)
                    ldsm_x4(whi[2][0], whi[2][1], wlo[2][0], wlo[2][1],
                            sA + (uint32_t)bRB2 + colWb);
                }
#pragma unroll
                for (int mi = 0; mi < 2; mi++)
#pragma unroll
                    for (int ni = 0; ni < 3; ni++)
                        mma16816(acc[mi][ni], hhi[mi], whi[ni][0], whi[ni][1]);
#pragma unroll
                for (int mi = 0; mi < 2; mi++)
#pragma unroll
                    for (int ni = 0; ni < 3; ni++)
                        mma16816(acc[mi][ni], hlo[mi], whi[ni][0], whi[ni][1]);
#pragma unroll
                for (int mi = 0; mi < 2; mi++)
#pragma unroll
                    for (int ni = 0; ni < 3; ni++)
                        mma16816(acc[mi][ni], hhi[mi], wlo[ni][0], wlo[ni][1]);
            }
            // no trailing sync: 3-buffer reuse distance makes it redundant
        }
        __syncthreads();   // all buffer reads done before pbuf alias write

        // ---- partials to smem (transposed): pbuf[w][gatecol][batch] ----
#pragma unroll
        for (int mi = 0; mi < 2; mi++) {
            int rb = mi * 16 + (lane >> 2);          // batch
#pragma unroll
            for (int ni = 0; ni < 3; ni++) {
                int cg = ni * 8 + (lane & 3) * 2;    // gatecol
                float* pb = pbuf + w * (32 * PSTR);
                pb[cg * PSTR + rb]           = acc[mi][ni][0];
                pb[(cg + 1) * PSTR + rb]     = acc[mi][ni][1];
                pb[cg * PSTR + rb + 8]       = acc[mi][ni][2];
                pb[(cg + 1) * PSTR + rb + 8] = acc[mi][ni][3];
            }
        }
        __syncthreads();

        // ---- reduce 8 partials + gate math (warp = cc, lane = bb) ----
        {
            const int cc = w, bb = lane;
            float pre0 = gxr0, pre1 = gxr1, pre2 = gxr2;
#pragma unroll
            for (int u = 0; u < 8; u++) {
                const float* pb = pbuf + u * (32 * PSTR) + bb;
                pre0 += pb[(cc)      * PSTR];
                pre1 += pb[(8 + cc)  * PSTR];
                pre2 += pb[(16 + cc) * PSTR];
            }
            float f  = sigm_f(pre0);
            float o  = sigm_f(pre1);
            float ch = tanh_f(pre2);
            float cold = csm[cc * 32 + bb];
            float cn = f * (cold - ch) + ch;
            float hn = o * tanh_f(cn);
            csm[cc * 32 + bb] = cn;
            tbuf[bb * 9 + cc] = hn;

            int colg = c0col + cc;
            out[((size_t)bb * S_DIM + t) * H_DIM + colg] = hn;
            if (t == S_DIM - 1 && wantTail) {
                size_t base2 = (size_t)B_DIM * S_DIM * H_DIM;
                out[base2 + (size_t)bb * H_DIM + colg] = hn;
                out[base2 + (size_t)B_DIM * H_DIM + (size_t)bb * H_DIM + colg] = cn;
            }
        }
        __syncthreads();

        // ---- h -> bf16 hi/lo, coalesced store to next epoch ----
        {
            int bb = tid >> 3, cc = tid & 7;
            float v = tbuf[bb * 9 + cc];
            __nv_bfloat16 hh = __float2bfloat16(v);
            __nv_bfloat16 hl = __float2bfloat16(v - __bfloat162float(hh));
            unsigned short uh = *(unsigned short*)&hh;
            unsigned short ul = *(unsigned short*)&hl;
            size_t go = (size_t)bb * H_DIM + c0col + cc;
            asm volatile("st.global.cg.u16 [%0], %1;"
                         :: "l"(&g_hbhi[epn][go]), "h"(uh) : "memory");
            asm volatile("st.global.cg.u16 [%0], %1;"
                         :: "l"(&g_hblo[epn][go]), "h"(ul) : "memory");
        }

        if (t < S_DIM - 1) gridSync(nb);
    }
}

// ---------------- launch ----------------
extern "C" void kernel_launch(void* const* d_in, const int* in_sizes, int n_in,
                              void* d_out, int out_size) {
    const float* x  = (const float*)d_in[0];
    const float* h0 = (const float*)d_in[1];
    const float* c0 = (const float*)d_in[2];
    const float* Wf = (const float*)d_in[3];
    const float* bf = (const float*)d_in[4];
    const float* Wo = (const float*)d_in[5];
    const float* bo = (const float*)d_in[6];
    const float* Wc = (const float*)d_in[7];
    const float* bc = (const float*)d_in[8];
    float* out = (float*)d_out;

    cudaFuncSetAttribute(mma_gemm,
                         cudaFuncAttributeMaxDynamicSharedMemorySize, GSMEM_BYTES);
    cudaFuncSetAttribute(lstm_recurrent,
                         cudaFuncAttributeMaxDynamicSharedMemorySize, RSMEM_BYTES);

    cvt_x<<<(B_DIM * S_DIM * I_DIM + 255) / 256, 256>>>(x);
    cvt_w<<<(3 * H_DIM * I_DIM + 255) / 256, 256>>>(Wf, Wo, Wc);
    mma_gemm<<<dim3(24, 256), 256, GSMEM_BYTES>>>(bf, bo, bc);
    init_hb<<<(B_DIM * H_DIM + 255) / 256, 256>>>(h0);
    lstm_recurrent<<<NB_CTA, NTH, RSMEM_BYTES>>>(Wf, Wo, Wc, c0, out, out_size);
}